// round 15
// baseline (speedup 1.0000x reference)
#include <cuda_runtime.h>
#include <cuda_fp16.h>
#include <math.h>
#include <stdint.h>

#define HB 512
#define SB 4096
#define BB 32
#define MT 128                         // M-tile rows
#define NT 32                          // tiles per batch (4096/128)

// ---------------- k_logits smem layout (single-pass N=512) ----------------
#define XLDA 520                       // fp16 elems per X row (padded, 16B-aligned rows)
#define WLDA 40                        // fp16 elems per B row (32-K chunk + 8 pad, 80B rows)
#define XS_OFF   0
#define XS_BYTES (MT*XLDA*2)           // 133120
#define BS_OFF   XS_BYTES
#define BS_BYTES (512*WLDA*2)          // 40960 per buffer, x2 (512 N-rows x 32 K)
#define F_OFF    (BS_OFF + 2*BS_BYTES) // 215040
#define TBS_OFF  F_OFF                 // 512 floats: q[b,:]+bq+br
#define VS_OFF   (F_OFF + 2048)        // 512 floats: V
#define LSUM_OFF (F_OFF + 4096)        // 128 floats (logits -> exp weights)
#define RED_OFF  (F_OFF + 4608)        // 8 floats scratch
#define PART_OFF (F_OFF + 4640)        // 1024 floats: 2-half weighted-sum partials
#define K1_SMEM  (F_OFF + 8736)        // 223776 B = 218.5 KB -> 1 CTA/SM

// ---------------- scratch ----------------
__device__ float   g_qb[BB*HB];
__device__ __half  g_Wrh[HB*HB];
__device__ float   g_pvec[BB*NT*HB];   // per-tile partial weighted-x sums
__device__ float   g_pm[BB*NT];        // per-tile logit max
__device__ float   g_pz[BB*NT];        // per-tile exp sum

// ---------------- helpers ----------------
static __device__ __forceinline__ uint32_t s2u(const void* p) {
    uint32_t a;
    asm("{ .reg .u64 t; cvta.to.shared.u64 t, %1; cvt.u32.u64 %0, t; }" : "=r"(a) : "l"(p));
    return a;
}
static __device__ __forceinline__ float tanha(float x) {
    float y; asm("tanh.approx.f32 %0, %1;" : "=f"(y) : "f"(x)); return y;
}
#define LDSM4(r0,r1,r2,r3,a) \
    asm volatile("ldmatrix.sync.aligned.m8n8.x4.shared.b16 {%0,%1,%2,%3}, [%4];" \
                 : "=r"(r0),"=r"(r1),"=r"(r2),"=r"(r3) : "r"(a))
#define MMAF16(c0,c1, a0,a1,a2,a3, b0,b1) \
    asm volatile("mma.sync.aligned.m16n8k16.row.col.f16.f16.f16.f16 " \
                 "{%0,%1}, {%2,%3,%4,%5}, {%6,%7}, {%0,%1};\n" \
                 : "+r"(c0), "+r"(c1) \
                 : "r"(a0), "r"(a1), "r"(a2), "r"(a3), "r"(b0), "r"(b1))
#define CPASYNC16(d, s) \
    asm volatile("cp.async.cg.shared.global [%0], [%1], 16;" :: "r"(d), "l"(s))

// ---------------- prep: blocks 0-255 Wr->fp16; 256-511 qb warp-per-h (unchanged) ----
__global__ void k_prep(const float* __restrict__ Wq, const float* __restrict__ Wr,
                       const float* __restrict__ query, const float* __restrict__ bq,
                       const float* __restrict__ br) {
    const int bid = blockIdx.x, tid = threadIdx.x;       // 512 x 256

    if (bid < 256) {                                     // Wr -> fp16, float4-coalesced
        const int i4 = bid*256 + tid;
        float4 v = *(const float4*)(Wr + (size_t)i4*4);
        __half2 p0 = __floats2half2_rn(v.x, v.y);
        __half2 p1 = __floats2half2_rn(v.z, v.w);
        uint2 u; u.x = *(uint32_t*)&p0; u.y = *(uint32_t*)&p1;
        *(uint2*)(g_Wrh + (size_t)i4*4) = u;
        return;
    }

    const int L  = bid - 256;
    const int tx = tid & 31, ty = tid >> 5;
    const int h  = (L & 63)*8 + ty;
    const int b0 = (L >> 6)*8;
    float wq[16];
    const float* wrow = Wq + (size_t)h * HB;
    #pragma unroll
    for (int m = 0; m < 16; ++m) wq[m] = wrow[tx + 32*m];
    #pragma unroll
    for (int b = 0; b < 8; ++b) {
        const float* qrow = query + (size_t)(b0 + b) * HB;
        float a = 0.f;
        #pragma unroll
        for (int m = 0; m < 16; ++m) a += wq[m] * qrow[tx + 32*m];
        #pragma unroll
        for (int o = 16; o; o >>= 1) a += __shfl_xor_sync(~0u, a, o);
        if (tx == 0) g_qb[(b0 + b)*HB + h] = a + bq[h] + br[h];
    }
}

// ---------------- fused logits, single-pass N=512 ----------------
__global__ void __launch_bounds__(512, 1)
k_logits(const float* __restrict__ ref, const float* __restrict__ V) {
    extern __shared__ char smem[];
    const int tid = threadIdx.x, lane = tid & 31, w = tid >> 5;
    const int wm = w & 1;          // M group: rows wm*64..+63 (4 mt tiles of 16)
    const int wn = w >> 1;         // N group: cols wn*64..+63 of 512
    const uint32_t sb = s2u(smem);

    float* tbs  = (float*)(smem + TBS_OFF);
    float* Vs   = (float*)(smem + VS_OFF);
    float* lsum = (float*)(smem + LSUM_OFF);
    float* red  = (float*)(smem + RED_OFF);
    float* part = (float*)(smem + PART_OFF);

    const long row0 = (long)blockIdx.x * MT;
    const int  b    = (int)(row0 >> 12);
    const float4* Xg = (const float4*)(ref + row0 * HB);

    // ---- stage macro: Wr chunk kb (rows 0..511, cols kb*32..+31) -> buffer kb&1 ----
    #define STAGE(kb_) do {                                                      \
        const uint32_t dstb = sb + BS_OFF + ((kb_) & 1)*BS_BYTES;                \
        const __half* srcb = g_Wrh + (kb_)*32;                                   \
        _Pragma("unroll")                                                        \
        for (int j_ = 0; j_ < 4; ++j_) {                                         \
            int i_ = tid + 512*j_; int r_ = i_ >> 2, c8_ = i_ & 3;               \
            CPASYNC16(dstb + (uint32_t)(r_*(WLDA*2) + c8_*16),                   \
                      srcb + (size_t)r_*HB + c8_*8);                             \
        }                                                                        \
        asm volatile("cp.async.commit_group;" ::: "memory");                     \
    } while (0)

    // ---- X chunk c (64 cols): blocking LDG+convert+STS ----
    #define LOADX(c_) do {                                                       \
        _Pragma("unroll")                                                        \
        for (int j_ = 0; j_ < 4; ++j_) {                                         \
            int i_ = tid + 512*j_; int r_ = i_ >> 4, c4_ = i_ & 15;              \
            float4 v_ = Xg[(size_t)r_*128 + (c_)*16 + c4_];                      \
            __half2 p0_ = __floats2half2_rn(v_.x, v_.y);                         \
            __half2 p1_ = __floats2half2_rn(v_.z, v_.w);                         \
            uint2 u_; u_.x = *(uint32_t*)&p0_; u_.y = *(uint32_t*)&p1_;          \
            *(uint2*)(smem + XS_OFF + ((size_t)r_*XLDA + (c_)*64 + c4_*4)*2) = u_; \
        }                                                                        \
    } while (0)

    STAGE(0);
    LOADX(0); LOADX(1);
    for (int i = tid; i < HB; i += 512) { tbs[i] = g_qb[b*HB + i]; Vs[i] = V[i]; }
    if (tid < MT) lsum[tid] = 0.f;

    // ---- ldmatrix lane addresses ----
    // A: rows wm*64 + mt*16 + (lane&15), col byte (lane>>4)*16
    const uint32_t a_addr = sb + XS_OFF +
        (uint32_t)(((wm*64 + (lane & 15))*XLDA + ((lane >> 4) << 3)) * 2);
    // B (per ntp): rows wn*64 + ntp*16 + ((lane>>4)<<3) + (lane&7), col ((lane>>3)&1)*8
    const uint32_t b_addr0 = sb + BS_OFF +
        (uint32_t)(((wn*64 + ((lane >> 4) << 3) + (lane & 7))*WLDA
                    + (((lane >> 3) & 1) << 3)) * 2);

    uint32_t acc[4][8][2];             // f16x2 accumulators, 64 regs
    #pragma unroll
    for (int mt = 0; mt < 4; ++mt)
        #pragma unroll
        for (int nt = 0; nt < 8; ++nt) { acc[mt][nt][0] = 0u; acc[mt][nt][1] = 0u; }

    for (int kb = 0; kb < 16; ++kb) {              // 32-K windows
        asm volatile("cp.async.wait_group 0;" ::: "memory");
        __syncthreads();
        if (kb < 15) STAGE(kb + 1);

        const bool doX = (kb < 12) && ((kb & 1) == 0);
        const int xc = (kb >> 1) + 2;
        float4 xr[4];
        if (doX) {
            #pragma unroll
            for (int j = 0; j < 4; ++j) {
                int i = tid + 512*j; int r = i >> 4, c4 = i & 15;
                xr[j] = Xg[(size_t)r*128 + xc*16 + c4];
            }
        }

        const uint32_t abase = (uint32_t)(kb*64);          // kb*32 elems * 2B
        const uint32_t bbase = (uint32_t)((kb & 1)*BS_BYTES);

        #pragma unroll
        for (int kk = 0; kk < 2; ++kk) {
            const uint32_t ko = (uint32_t)(kk*32);         // kk*16 elems * 2B
            uint32_t af[16];
            #pragma unroll
            for (int mt = 0; mt < 4; ++mt)
                LDSM4(af[mt*4+0],af[mt*4+1],af[mt*4+2],af[mt*4+3],
                      a_addr + abase + ko + (uint32_t)(mt*16*XLDA*2));
            #pragma unroll
            for (int ntp = 0; ntp < 4; ++ntp) {
                uint32_t bf0, bf1, bf2, bf3;
                LDSM4(bf0, bf1, bf2, bf3,
                      b_addr0 + bbase + ko + (uint32_t)(ntp*16*WLDA*2));
                #pragma unroll
                for (int mt = 0; mt < 4; ++mt) {
                    MMAF16(acc[mt][ntp*2+0][0], acc[mt][ntp*2+0][1],
                           af[mt*4+0],af[mt*4+1],af[mt*4+2],af[mt*4+3], bf0, bf1);
                    MMAF16(acc[mt][ntp*2+1][0], acc[mt][ntp*2+1][1],
                           af[mt*4+0],af[mt*4+1],af[mt*4+2],af[mt*4+3], bf2, bf3);
                }
            }
        }

        if (doX) {
            #pragma unroll
            for (int j = 0; j < 4; ++j) {
                int i = tid + 512*j; int r = i >> 4, c4 = i & 15;
                __half2 p0 = __floats2half2_rn(xr[j].x, xr[j].y);
                __half2 p1 = __floats2half2_rn(xr[j].z, xr[j].w);
                uint2 u; u.x = *(uint32_t*)&p0; u.y = *(uint32_t*)&p1;
                *(uint2*)(smem + XS_OFF + ((size_t)r*XLDA + xc*64 + c4*4)*2) = u;
            }
        }
    }
    #undef STAGE
    #undef LOADX

    // ---- logits += V[n]*tanh(r + qb[n]) (single epilogue over all 512 cols) ----
    {
        float rs[4][2] = {{0.f,0.f},{0.f,0.f},{0.f,0.f},{0.f,0.f}};
        #pragma unroll
        for (int mt = 0; mt < 4; ++mt)
            #pragma unroll
            for (int nt = 0; nt < 8; ++nt) {
                const int col0 = wn*64 + nt*8 + ((lane & 3) << 1);
                #pragma unroll
                for (int h = 0; h < 2; ++h) {
                    float2 v = __half22float2(*(__half2*)&acc[mt][nt][h]);
                    rs[mt][h] += tanha(v.x + tbs[col0])     * Vs[col0]
                               + tanha(v.y + tbs[col0 + 1]) * Vs[col0 + 1];
                }
            }
        #pragma unroll
        for (int mt = 0; mt < 4; ++mt)
            #pragma unroll
            for (int h = 0; h < 2; ++h) {
                float v = rs[mt][h];
                v += __shfl_xor_sync(0xffffffffu, v, 1);
                v += __shfl_xor_sync(0xffffffffu, v, 2);
                if ((lane & 3) == 0)
                    atomicAdd(&lsum[wm*64 + mt*16 + h*8 + (lane >> 2)], v);
            }
    }

    // ---- split-softmax epilogue: m_t, e_s, Z_t, vec_t = sum_s e_s * x_s ----
    __syncthreads();
    if (tid < MT) {
        float v = lsum[tid];
        #pragma unroll
        for (int o = 16; o; o >>= 1) v = fmaxf(v, __shfl_xor_sync(~0u, v, o));
        if (lane == 0) red[w] = v;
    }
    __syncthreads();
    if (tid == 0) red[4] = fmaxf(fmaxf(red[0], red[1]), fmaxf(red[2], red[3]));
    __syncthreads();
    const float M = red[4];
    if (tid < MT) {
        float e = __expf(lsum[tid] - M);
        lsum[tid] = e;
        float z = e;
        #pragma unroll
        for (int o = 16; o; o >>= 1) z += __shfl_xor_sync(~0u, z, o);
        if (lane == 0) red[w] = z;
    }
    __syncthreads();
    if (tid == 0) {
        g_pm[blockIdx.x] = M;
        g_pz[blockIdx.x] = (red[0] + red[1]) + (red[2] + red[3]);
    }
    {
        const int c2 = tid & 255, rh = tid >> 8;
        float a0 = 0.f, a1 = 0.f;
        #pragma unroll 4
        for (int s = rh*64; s < rh*64 + 64; ++s) {
            const float e = lsum[s];
            float2 xf = __half22float2(*(__half2*)(smem + XS_OFF + ((size_t)s*XLDA + 2*c2)*2));
            a0 += e * xf.x; a1 += e * xf.y;
        }
        *(float2*)&part[rh*512 + c2*2] = make_float2(a0, a1);
    }
    __syncthreads();
    if (tid < 256) {
        float2 p0 = *(float2*)&part[tid*2];
        float2 p1 = *(float2*)&part[512 + tid*2];
        *(float2*)(g_pvec + (size_t)blockIdx.x*HB + 2*tid) =
            make_float2(p0.x + p1.x, p0.y + p1.y);
    }
}

// ---------------- combine + output GEMV (warp-per-h over row-major Wr) ----------------
__global__ void k_combout(const float* __restrict__ Wr, const float* __restrict__ br,
                          float* __restrict__ out) {
    const int b = blockIdx.y, tid = threadIdx.x;      // grid (4,32) x 256
    const int lane = tid & 31, wp = tid >> 5;         // 8 warps
    __shared__ float sc[NT];
    __shared__ float As[HB];
    __shared__ float bcM, bcZ;
    if (tid < NT) {
        float m = g_pm[b*NT + tid];
        float v = m;
        #pragma unroll
        for (int o = 16; o; o >>= 1) v = fmaxf(v, __shfl_xor_sync(~0u, v, o));
        if (tid == 0) bcM = v;
        __syncwarp();
        float s = __expf(m - bcM);
        sc[tid] = s;
        float z = s * g_pz[b*NT + tid];
        #pragma unroll
        for (int o = 16; o; o >>= 1) z += __shfl_xor_sync(~0u, z, o);
        if (tid == 0) bcZ = z;
    }
    __syncthreads();
    const float invZ = 1.f / bcZ;
    {
        float2 a = make_float2(0.f, 0.f);
        #pragma unroll 4
        for (int t = 0; t < NT; ++t) {
            const float s = sc[t];
            float2 p = *(const float2*)(g_pvec + (size_t)(b*NT + t)*HB + tid*2);
            a.x += s*p.x; a.y += s*p.y;
        }
        a.x *= invZ; a.y *= invZ;
        *(float2*)&As[tid*2] = a;
    }
    __syncthreads();
    const int h0 = blockIdx.x*128;
    for (int hh = 0; hh < 16; ++hh) {
        const int h = h0 + wp*16 + hh;
        const float* wrow = Wr + (size_t)h * HB;
        float a = 0.f;
        #pragma unroll
        for (int m = 0; m < 16; ++m) a += As[lane + 32*m] * wrow[lane + 32*m];
        #pragma unroll
        for (int o = 16; o; o >>= 1) a += __shfl_xor_sync(~0u, a, o);
        if (lane == 0) out[b*HB + h] = a + br[h];
    }
}

// ---------------- launch ----------------
extern "C" void kernel_launch(void* const* d_in, const int* in_sizes, int n_in,
                              void* d_out, int out_size) {
    const float* query = (const float*)d_in[0];
    const float* ref   = (const float*)d_in[1];
    const float* Wq    = (const float*)d_in[2];
    const float* bq    = (const float*)d_in[3];
    const float* Wr    = (const float*)d_in[4];
    const float* br    = (const float*)d_in[5];
    const float* V     = (const float*)d_in[6];
    float* out = (float*)d_out;

    cudaFuncSetAttribute(k_logits, cudaFuncAttributeMaxDynamicSharedMemorySize, K1_SMEM);

    k_prep   <<<512, 256>>>(Wq, Wr, query, bq, br);
    k_logits <<<(BB*SB)/MT, 512, K1_SMEM>>>(ref, V);
    k_combout<<<dim3(4, BB), 256>>>(Wr, br, out);
}

// round 16
// speedup vs baseline: 1.1736x; 1.1736x over previous
#include <cuda_runtime.h>
#include <cuda_fp16.h>
#include <math.h>
#include <stdint.h>

#define HB 512
#define SB 4096
#define BB 32
#define MT 128                         // M-tile rows
#define NT 32                          // tiles per batch (4096/128)

// ---------------- k_logits smem layout (R11/R14 config) ----------------
#define XLDA 520                       // fp16 elems per X row (padded)
#define WLDA 72                        // fp16 elems per B row (padded)
#define XS_OFF   0
#define XS_BYTES (MT*XLDA*2)           // 133120
#define BS_OFF   XS_BYTES
#define BS_BYTES (256*WLDA*2)          // 36864 per buffer, x2 (256 N-rows x 64 K)
#define F_OFF    (BS_OFF + 2*BS_BYTES) // 206848
#define TBS_OFF  F_OFF                 // 512 floats: q[b,:]+bq+br
#define VS_OFF   (F_OFF + 2048)        // 512 floats: V
#define LSUM_OFF (F_OFF + 4096)        // 128 floats (logits -> exp weights)
#define RED_OFF  (F_OFF + 4608)        // 8 floats scratch
#define PART_OFF (F_OFF + 4640)        // 1024 floats: 2-half weighted-sum partials
#define K1_SMEM  (F_OFF + 8736)        // ~210.5 KB -> 1 CTA/SM

// ---------------- scratch ----------------
__device__ float   g_qb[BB*HB];
__device__ __half  g_Wrh[HB*HB];
__device__ float   g_pvec[BB*NT*HB];   // per-tile partial weighted-x sums
__device__ float   g_pm[BB*NT];        // per-tile logit max
__device__ float   g_pz[BB*NT];        // per-tile exp sum

// ---------------- helpers ----------------
static __device__ __forceinline__ uint32_t s2u(const void* p) {
    uint32_t a;
    asm("{ .reg .u64 t; cvta.to.shared.u64 t, %1; cvt.u32.u64 %0, t; }" : "=r"(a) : "l"(p));
    return a;
}
static __device__ __forceinline__ float tanha(float x) {
    float y; asm("tanh.approx.f32 %0, %1;" : "=f"(y) : "f"(x)); return y;
}
#define LDSM4(r0,r1,r2,r3,a) \
    asm volatile("ldmatrix.sync.aligned.m8n8.x4.shared.b16 {%0,%1,%2,%3}, [%4];" \
                 : "=r"(r0),"=r"(r1),"=r"(r2),"=r"(r3) : "r"(a))
#define MMAF16(c0,c1, a0,a1,a2,a3, b0,b1) \
    asm volatile("mma.sync.aligned.m16n8k16.row.col.f16.f16.f16.f16 " \
                 "{%0,%1}, {%2,%3,%4,%5}, {%6,%7}, {%0,%1};\n" \
                 : "+r"(c0), "+r"(c1) \
                 : "r"(a0), "r"(a1), "r"(a2), "r"(a3), "r"(b0), "r"(b1))
#define CPASYNC16(d, s) \
    asm volatile("cp.async.cg.shared.global [%0], [%1], 16;" :: "r"(d), "l"(s))

// ---------------- prep: blocks 0-255 Wr->fp16; 256-767 qb (4 batches/block) ----
__global__ void k_prep(const float* __restrict__ Wq, const float* __restrict__ Wr,
                       const float* __restrict__ query, const float* __restrict__ bq,
                       const float* __restrict__ br) {
    const int bid = blockIdx.x, tid = threadIdx.x;       // 768 x 256

    if (bid < 256) {                                     // Wr -> fp16, float4-coalesced
        const int i4 = bid*256 + tid;
        float4 v = *(const float4*)(Wr + (size_t)i4*4);
        __half2 p0 = __floats2half2_rn(v.x, v.y);
        __half2 p1 = __floats2half2_rn(v.z, v.w);
        uint2 u; u.x = *(uint32_t*)&p0; u.y = *(uint32_t*)&p1;
        *(uint2*)(g_Wrh + (size_t)i4*4) = u;
        return;
    }

    // qb slice: block L handles h = (L&63)*8 + ty, b = (L>>6)*4 .. +3
    const int L  = bid - 256;                            // 0..511
    const int tx = tid & 31, ty = tid >> 5;
    const int h  = (L & 63)*8 + ty;
    const int b0 = (L >> 6)*4;
    float wq[16];
    const float* wrow = Wq + (size_t)h * HB;
    #pragma unroll
    for (int m = 0; m < 16; ++m) wq[m] = wrow[tx + 32*m];
    #pragma unroll
    for (int b = 0; b < 4; ++b) {
        const float* qrow = query + (size_t)(b0 + b) * HB;
        float a = 0.f;
        #pragma unroll
        for (int m = 0; m < 16; ++m) a += wq[m] * qrow[tx + 32*m];
        #pragma unroll
        for (int o = 16; o; o >>= 1) a += __shfl_xor_sync(~0u, a, o);
        if (tx == 0) g_qb[(b0 + b)*HB + h] = a + bq[h] + br[h];
    }
}

// ---------------- fused logits + split-softmax partial weighted sum ----------------
__global__ void __launch_bounds__(512, 1)
k_logits(const float* __restrict__ ref, const float* __restrict__ V) {
    extern __shared__ char smem[];
    const int tid = threadIdx.x, lane = tid & 31, w = tid >> 5;
    const int wm = w & 3;          // M group: rows wm*32..+31 (2 mt tiles of 16)
    const int wn = w >> 2;         // N group: cols wn*64..+63 within a 256-chunk
    const uint32_t sb = s2u(smem);

    float* tbs  = (float*)(smem + TBS_OFF);
    float* Vs   = (float*)(smem + VS_OFF);
    float* lsum = (float*)(smem + LSUM_OFF);
    float* red  = (float*)(smem + RED_OFF);
    float* part = (float*)(smem + PART_OFF);

    const long row0 = (long)blockIdx.x * MT;
    const int  b    = (int)(row0 >> 12);
    const float4* Xg = (const float4*)(ref + row0 * HB);

    #define STAGE(idx_) do {                                                     \
        const int nc_ = (idx_) >> 3, kb_ = (idx_) & 7;                           \
        const uint32_t dstb = sb + BS_OFF + ((idx_) & 1)*BS_BYTES;               \
        const __half* srcb = g_Wrh + (size_t)(nc_*256)*HB + kb_*64;              \
        _Pragma("unroll")                                                        \
        for (int j_ = 0; j_ < 4; ++j_) {                                         \
            int i_ = tid + 512*j_; int r_ = i_ >> 3, c8_ = i_ & 7;               \
            CPASYNC16(dstb + (uint32_t)((r_*WLDA + c8_*8)*2),                    \
                      srcb + (size_t)r_*HB + c8_*8);                             \
        }                                                                        \
        asm volatile("cp.async.commit_group;" ::: "memory");                     \
    } while (0)

    #define LOADX(c_) do {                                                       \
        _Pragma("unroll")                                                        \
        for (int j_ = 0; j_ < 4; ++j_) {                                         \
            int i_ = tid + 512*j_; int r_ = i_ >> 4, c4_ = i_ & 15;              \
            float4 v_ = Xg[(size_t)r_*128 + (c_)*16 + c4_];                      \
            __half2 p0_ = __floats2half2_rn(v_.x, v_.y);                         \
            __half2 p1_ = __floats2half2_rn(v_.z, v_.w);                         \
            uint2 u_; u_.x = *(uint32_t*)&p0_; u_.y = *(uint32_t*)&p1_;          \
            *(uint2*)(smem + XS_OFF + ((size_t)r_*XLDA + (c_)*64 + c4_*4)*2) = u_; \
        }                                                                        \
    } while (0)

    STAGE(0);
    LOADX(0);                           // only chunk 0 blocking; chunks 1..7 pipelined
    for (int i = tid; i < HB; i += 512) { tbs[i] = g_qb[b*HB + i]; Vs[i] = V[i]; }
    if (tid < MT) lsum[tid] = 0.f;

    const uint32_t a_addr = sb + XS_OFF +
        (uint32_t)(((wm*32 + (lane & 15))*XLDA + ((lane >> 4) << 3)) * 2);
    uint32_t b_addr[4];
    #pragma unroll
    for (int ntp = 0; ntp < 4; ++ntp)
        b_addr[ntp] = sb + BS_OFF +
            (uint32_t)(((wn*64 + ntp*16 + ((lane >> 4) << 3) + (lane & 7))*WLDA
                        + (((lane >> 3) & 1) << 3)) * 2);

    for (int nc = 0; nc < 2; ++nc) {
        uint32_t acc[2][8][2];
        #pragma unroll
        for (int mt = 0; mt < 2; ++mt)
            #pragma unroll
            for (int nt = 0; nt < 8; ++nt) { acc[mt][nt][0] = 0u; acc[mt][nt][1] = 0u; }

        for (int kb = 0; kb < 8; ++kb) {
            const int idx = nc*8 + kb;
            asm volatile("cp.async.wait_group 0;" ::: "memory");
            __syncthreads();
            if (idx < 15) STAGE(idx + 1);

            // X chunk kb+1: LDG now, STS after MMA block; visible after next barrier
            const bool doX = (nc == 0) && (kb < 7);
            float4 xr[4];
            if (doX) {
                #pragma unroll
                for (int j = 0; j < 4; ++j) {
                    int i = tid + 512*j; int r = i >> 4, c4 = i & 15;
                    xr[j] = Xg[(size_t)r*128 + (kb + 1)*16 + c4];
                }
            }

            const uint32_t abase = (uint32_t)(kb*128);
            const uint32_t bbase = (uint32_t)((idx & 1)*BS_BYTES);

            #pragma unroll
            for (int kk = 0; kk < 4; ++kk) {
                const uint32_t ko = (uint32_t)(kk*32);
                uint32_t af[8], bf_[16];
                #pragma unroll
                for (int mt = 0; mt < 2; ++mt)
                    LDSM4(af[mt*4+0],af[mt*4+1],af[mt*4+2],af[mt*4+3],
                          a_addr + abase + ko + (uint32_t)(mt*16*XLDA*2));
                #pragma unroll
                for (int ntp = 0; ntp < 4; ++ntp)
                    LDSM4(bf_[ntp*4+0],bf_[ntp*4+1],bf_[ntp*4+2],bf_[ntp*4+3],
                          b_addr[ntp] + bbase + ko);
                #pragma unroll
                for (int nt = 0; nt < 8; ++nt) {
                    const uint32_t b0 = bf_[(nt >> 1)*4 + (nt & 1)*2 + 0];
                    const uint32_t b1 = bf_[(nt >> 1)*4 + (nt & 1)*2 + 1];
                    #pragma unroll
                    for (int mt = 0; mt < 2; ++mt)
                        MMAF16(acc[mt][nt][0], acc[mt][nt][1],
                               af[mt*4+0],af[mt*4+1],af[mt*4+2],af[mt*4+3], b0, b1);
                }
            }

            if (doX) {
                #pragma unroll
                for (int j = 0; j < 4; ++j) {
                    int i = tid + 512*j; int r = i >> 4, c4 = i & 15;
                    __half2 p0 = __floats2half2_rn(xr[j].x, xr[j].y);
                    __half2 p1 = __floats2half2_rn(xr[j].z, xr[j].w);
                    uint2 u; u.x = *(uint32_t*)&p0; u.y = *(uint32_t*)&p1;
                    *(uint2*)(smem + XS_OFF + ((size_t)r*XLDA + (kb + 1)*64 + c4*4)*2) = u;
                }
            }
        }

        float rs[2][2] = {{0.f,0.f},{0.f,0.f}};
        #pragma unroll
        for (int mt = 0; mt < 2; ++mt)
            #pragma unroll
            for (int nt = 0; nt < 8; ++nt) {
                const int col0 = nc*256 + wn*64 + nt*8 + ((lane & 3) << 1);
                #pragma unroll
                for (int h = 0; h < 2; ++h) {
                    float2 v = __half22float2(*(__half2*)&acc[mt][nt][h]);
                    rs[mt][h] += tanha(v.x + tbs[col0])     * Vs[col0]
                               + tanha(v.y + tbs[col0 + 1]) * Vs[col0 + 1];
                }
            }
        #pragma unroll
        for (int mt = 0; mt < 2; ++mt)
            #pragma unroll
            for (int h = 0; h < 2; ++h) {
                float v = rs[mt][h];
                v += __shfl_xor_sync(0xffffffffu, v, 1);
                v += __shfl_xor_sync(0xffffffffu, v, 2);
                if ((lane & 3) == 0)
                    atomicAdd(&lsum[wm*32 + mt*16 + h*8 + (lane >> 2)], v);
            }
    }
    #undef STAGE
    #undef LOADX

    __syncthreads();
    if (tid < MT) {
        float v = lsum[tid];
        #pragma unroll
        for (int o = 16; o; o >>= 1) v = fmaxf(v, __shfl_xor_sync(~0u, v, o));
        if (lane == 0) red[w] = v;
    }
    __syncthreads();
    if (tid == 0) red[4] = fmaxf(fmaxf(red[0], red[1]), fmaxf(red[2], red[3]));
    __syncthreads();
    const float M = red[4];
    if (tid < MT) {
        float e = __expf(lsum[tid] - M);
        lsum[tid] = e;
        float z = e;
        #pragma unroll
        for (int o = 16; o; o >>= 1) z += __shfl_xor_sync(~0u, z, o);
        if (lane == 0) red[w] = z;
    }
    __syncthreads();
    if (tid == 0) {
        g_pm[blockIdx.x] = M;
        g_pz[blockIdx.x] = (red[0] + red[1]) + (red[2] + red[3]);
    }
    {
        const int c2 = tid & 255, rh = tid >> 8;
        float a0 = 0.f, a1 = 0.f;
        #pragma unroll 4
        for (int s = rh*64; s < rh*64 + 64; ++s) {
            const float e = lsum[s];
            float2 xf = __half22float2(*(__half2*)(smem + XS_OFF + ((size_t)s*XLDA + 2*c2)*2));
            a0 += e * xf.x; a1 += e * xf.y;
        }
        *(float2*)&part[rh*512 + c2*2] = make_float2(a0, a1);
    }
    __syncthreads();
    if (tid < 256) {
        float2 p0 = *(float2*)&part[tid*2];
        float2 p1 = *(float2*)&part[512 + tid*2];
        *(float2*)(g_pvec + (size_t)blockIdx.x*HB + 2*tid) =
            make_float2(p0.x + p1.x, p0.y + p1.y);
    }
}

// ---------------- combine + output GEMV (warp-per-h over row-major Wr) ----------------
__global__ void k_combout(const float* __restrict__ Wr, const float* __restrict__ br,
                          float* __restrict__ out) {
    const int b = blockIdx.y, tid = threadIdx.x;      // grid (4,32) x 256
    const int lane = tid & 31, wp = tid >> 5;         // 8 warps
    __shared__ float sc[NT];
    __shared__ float As[HB];
    __shared__ float bcM, bcZ;
    if (tid < NT) {
        float m = g_pm[b*NT + tid];
        float v = m;
        #pragma unroll
        for (int o = 16; o; o >>= 1) v = fmaxf(v, __shfl_xor_sync(~0u, v, o));
        if (tid == 0) bcM = v;
        __syncwarp();
        float s = __expf(m - bcM);
        sc[tid] = s;
        float z = s * g_pz[b*NT + tid];
        #pragma unroll
        for (int o = 16; o; o >>= 1) z += __shfl_xor_sync(~0u, z, o);
        if (tid == 0) bcZ = z;
    }
    __syncthreads();
    const float invZ = 1.f / bcZ;
    {
        float2 a = make_float2(0.f, 0.f);
        #pragma unroll 4
        for (int t = 0; t < NT; ++t) {
            const float s = sc[t];
            float2 p = *(const float2*)(g_pvec + (size_t)(b*NT + t)*HB + tid*2);
            a.x += s*p.x; a.y += s*p.y;
        }
        a.x *= invZ; a.y *= invZ;
        *(float2*)&As[tid*2] = a;
    }
    __syncthreads();
    const int h0 = blockIdx.x*128;
    for (int hh = 0; hh < 16; ++hh) {
        const int h = h0 + wp*16 + hh;
        const float* wrow = Wr + (size_t)h * HB;
        float a = 0.f;
        #pragma unroll
        for (int m = 0; m < 16; ++m) a += As[lane + 32*m] * wrow[lane + 32*m];
        #pragma unroll
        for (int o = 16; o; o >>= 1) a += __shfl_xor_sync(~0u, a, o);
        if (lane == 0) out[b*HB + h] = a + br[h];
    }
}

// ---------------- launch ----------------
extern "C" void kernel_launch(void* const* d_in, const int* in_sizes, int n_in,
                              void* d_out, int out_size) {
    const float* query = (const float*)d_in[0];
    const float* ref   = (const float*)d_in[1];
    const float* Wq    = (const float*)d_in[2];
    const float* bq    = (const float*)d_in[3];
    const float* Wr    = (const float*)d_in[4];
    const float* br    = (const float*)d_in[5];
    const float* V     = (const float*)d_in[6];
    float* out = (float*)d_out;

    cudaFuncSetAttribute(k_logits, cudaFuncAttributeMaxDynamicSharedMemorySize, K1_SMEM);

    k_prep   <<<768, 256>>>(Wq, Wr, query, bq, br);
    k_logits <<<(BB*SB)/MT, 512, K1_SMEM>>>(ref, V);
    k_combout<<<dim3(4, BB), 256>>>(Wr, br, out);
}